// round 5
// baseline (speedup 1.0000x reference)
#include <cuda_runtime.h>

#define BB 64
#define TT 4096
#define DD 128
#define HH 128
#define GG 384            // 3*H, gates [r, z, n]

#define N_REC 32          // rec CTAs per layer, 2 batches each
#define N_G   42          // gemm CTAs per layer
// roles: [0,32) rec0, [32,64) rec1, [64,106) gemm0, [106,148) gemm1

typedef unsigned long long u64;

// Scratch (device globals — no allocation allowed).
__device__ float g_gi0[(size_t)TT * BB * GG];
__device__ float g_gi1[(size_t)TT * BB * GG];
__device__ float g_h0 [(size_t)TT * BB * HH];
__device__ unsigned g_f_gi0[TT];   // gi0[t] ready (target 1)
__device__ unsigned g_f_h0 [TT];   // h0[t] ready  (target N_REC)
__device__ unsigned g_f_gi1[TT];   // gi1[t] ready (target 1)

// ---- packed f32x2 + activation helpers -----------------------------------
__device__ __forceinline__ void fma2(u64& d, u64 a, u64 b) {
    asm("fma.rn.f32x2 %0, %1, %2, %0;" : "+l"(d) : "l"(a), "l"(b));
}
__device__ __forceinline__ u64 f2u(float x, float y) {
    u64 v; asm("mov.b64 %0, {%1,%2};" : "=l"(v) : "f"(x), "f"(y)); return v;
}
__device__ __forceinline__ float hsum(u64 a, u64 b) {
    float xl, xh, yl, yh;
    asm("mov.b64 {%0,%1}, %2;" : "=f"(xl), "=f"(xh) : "l"(a));
    asm("mov.b64 {%0,%1}, %2;" : "=f"(yl), "=f"(yh) : "l"(b));
    return (xl + xh) + (yl + yh);
}
__device__ __forceinline__ float fsig(float x) {
    return __fdividef(1.0f, 1.0f + __expf(-x));
}
__device__ __forceinline__ float ftanh(float x) {
    return 1.0f - __fdividef(2.0f, __expf(2.0f * x) + 1.0f);
}

// ---- flag primitives (gpu-scope release/acquire) -------------------------
__device__ __forceinline__ unsigned ld_acq(const unsigned* p) {
    unsigned v;
    asm volatile("ld.acquire.gpu.global.b32 %0, [%1];" : "=r"(v) : "l"(p));
    return v;
}
__device__ __forceinline__ void red_rel(unsigned* p) {
    asm volatile("red.release.gpu.global.add.u32 [%0], 1;" :: "l"(p) : "memory");
}
__device__ __forceinline__ void spin_ge(const unsigned* p, unsigned target) {
    while (ld_acq(p) < target) { __nanosleep(64); }
}

__global__ void zero_flags() {
    int i = blockIdx.x * blockDim.x + threadIdx.x;
    if (i < TT) { g_f_gi0[i] = 0; g_f_h0[i] = 0; g_f_gi1[i] = 0; }
}

// ---------------------------------------------------------------------------
struct SmemRec {
    float h[2][128];      // per-batch hidden state (double role by batch)
    float gh[2][384];     // per-batch pre-activation gh
};
struct SmemGemm {
    float x[4][128];
};
union SmemAll { SmemRec r; SmemGemm g; };

// ---------------------------------------------------------------------------
// GEMM role: stream gi[t] = act_row @ W^T + bias for t = t0, t0+N_G, ...
// ---------------------------------------------------------------------------
__device__ void gemm_role(SmemAll* sm,
                          const float* __restrict__ X,
                          const float* __restrict__ W,
                          const float* __restrict__ bias,
                          int which, int t0)
{
    const int j = threadIdx.x;

    u64 w[64];
    {
        const ulonglong2* wr = (const ulonglong2*)(W + (size_t)j * 128);
        #pragma unroll
        for (int k = 0; k < 32; k++) { ulonglong2 v = wr[k]; w[2*k] = v.x; w[2*k+1] = v.y; }
    }
    const float bj = bias[j];
    float* dst = which ? g_gi1 : g_gi0;
    unsigned* fout = which ? g_f_gi1 : g_f_gi0;

    for (int t = t0; t < TT; t += N_G) {
        if (which == 1) {
            if (j == 0) spin_ge(&g_f_h0[t], N_REC);
        }
        __syncthreads();

        for (int m = 0; m < BB; m += 4) {
            for (int i = j; i < 4 * 128; i += 384) {
                const int r = i >> 7, c = i & 127;
                const int b = m + r;
                const float* src = which
                    ? (g_h0 + ((size_t)t * BB + b) * HH)
                    : (X + ((size_t)b * TT + t) * DD);
                sm->g.x[r][c] = src[c];
            }
            __syncthreads();

            u64 a0 = f2u(bj, 0.f), a1 = f2u(bj, 0.f), a2 = f2u(bj, 0.f), a3 = f2u(bj, 0.f);
            const ulonglong2* r0 = (const ulonglong2*)sm->g.x[0];
            const ulonglong2* r1 = (const ulonglong2*)sm->g.x[1];
            const ulonglong2* r2 = (const ulonglong2*)sm->g.x[2];
            const ulonglong2* r3 = (const ulonglong2*)sm->g.x[3];
            #pragma unroll
            for (int k = 0; k < 32; k++) {
                ulonglong2 v0 = r0[k], v1 = r1[k], v2 = r2[k], v3 = r3[k];
                fma2(a0, v0.x, w[2*k]); fma2(a0, v0.y, w[2*k+1]);
                fma2(a1, v1.x, w[2*k]); fma2(a1, v1.y, w[2*k+1]);
                fma2(a2, v2.x, w[2*k]); fma2(a2, v2.y, w[2*k+1]);
                fma2(a3, v3.x, w[2*k]); fma2(a3, v3.y, w[2*k+1]);
            }
            dst[((size_t)t * BB + m + 0) * GG + j] = hsum(a0, f2u(0.f,0.f));
            dst[((size_t)t * BB + m + 1) * GG + j] = hsum(a1, f2u(0.f,0.f));
            dst[((size_t)t * BB + m + 2) * GG + j] = hsum(a2, f2u(0.f,0.f));
            dst[((size_t)t * BB + m + 3) * GG + j] = hsum(a3, f2u(0.f,0.f));
            __syncthreads();
        }
        if (j == 0) red_rel(&fout[t]);
    }
}

// ---------------------------------------------------------------------------
// REC role, batch-pipelined: 2 batches per CTA, half a step out of phase.
// Thread j owns W_hh row j (regs). Phase = one dot (one batch) + the OTHER
// batch's gate math on threads 0-127, then ONE __syncthreads.
// ---------------------------------------------------------------------------
__device__ void rec_role(SmemAll* smu,
                         const float* __restrict__ Whh,
                         const float* __restrict__ bhh,
                         int layer, int c,
                         float* __restrict__ hout)
{
    SmemRec* sm = &smu->r;
    const int j = threadIdx.x;
    const bool isGate = (j < 128);
    const int e = j & 127;
    const int b0 = 2 * c, b1 = 2 * c + 1;

    u64 w[64];
    {
        const ulonglong2* wr = (const ulonglong2*)(Whh + (size_t)j * 128);
        #pragma unroll
        for (int k = 0; k < 32; k++) { ulonglong2 v = wr[k]; w[2*k] = v.x; w[2*k+1] = v.y; }
    }
    const float bj = bhh[j];

    const float* gi = layer ? g_gi1 : g_gi0;
    const unsigned* fin = layer ? g_f_gi1 : g_f_gi0;
    const size_t S = (size_t)BB * GG;

    if (j < 128) { sm->h[0][j] = 0.0f; sm->h[1][j] = 0.0f; }
    if (j == 0) spin_ge(&fin[0], 1);
    __syncthreads();

    // gate-thread state: current gi values + previous h per batch
    float g0r = 0.f, g0z = 0.f, g0n = 0.f;   // batch b0, time t (for phase(t,1))
    float g1r = 0.f, g1z = 0.f, g1n = 0.f;   // batch b1, time t-1/t
    float hp0 = 0.f, hp1 = 0.f;

    if (isGate) {
        const float* p = gi + (size_t)b0 * GG;      // gi(b0, 0)
        g0r = p[e]; g0z = p[e + 128]; g0n = p[e + 256];
    }

    for (int t = 0; t < TT; t++) {
        // ============ phase (t,0): dot b0@t ; gates b1@(t-1) ============
        {
            if (isGate && t > 0) {
                const float r = fsig(sm->gh[1][e]       + g1r);
                const float z = fsig(sm->gh[1][e + 128] + g1z);
                const float n = ftanh(g1n + r * sm->gh[1][e + 256]);
                hp1 = n + z * (hp1 - n);
                sm->h[1][e] = hp1;
                if (layer == 0)
                    g_h0[((size_t)(t - 1) * BB + b1) * HH + e] = hp1;
            }
            if (isGate) {   // prefetch gi(b1, t) — flag fin[t] known (spun at t-1 / pre-loop)
                const float* p = gi + (size_t)t * S + (size_t)b1 * GG;
                g1r = p[e]; g1z = p[e + 128]; g1n = p[e + 256];
            }
            if (j == 383 && t + 1 < TT) spin_ge(&fin[t + 1], 1);

            u64 a0 = f2u(bj, 0.f), a1 = f2u(0.f, 0.f);
            const ulonglong2* hv = (const ulonglong2*)sm->h[0];
            #pragma unroll
            for (int k = 0; k < 32; k++) {
                ulonglong2 v = hv[k];
                fma2(a0, v.x, w[2*k]);
                fma2(a1, v.y, w[2*k+1]);
            }
            sm->gh[0][j] = hsum(a0, a1);
            __syncthreads();
            if (layer == 0 && j == 0 && t > 0) red_rel(&g_f_h0[t - 1]);
        }
        // ============ phase (t,1): dot b1@t ; gates b0@t ============
        {
            if (isGate) {
                const float r = fsig(sm->gh[0][e]       + g0r);
                const float z = fsig(sm->gh[0][e + 128] + g0z);
                const float n = ftanh(g0n + r * sm->gh[0][e + 256]);
                hp0 = n + z * (hp0 - n);
                sm->h[0][e] = hp0;
                if (layer == 0)
                    g_h0[((size_t)t * BB + b0) * HH + e] = hp0;
            }
            if (isGate && t + 1 < TT) {   // prefetch gi(b0, t+1); fin[t+1] spun in phase(t,0)
                const float* p = gi + (size_t)(t + 1) * S + (size_t)b0 * GG;
                g0r = p[e]; g0z = p[e + 128]; g0n = p[e + 256];
            }

            u64 a0 = f2u(bj, 0.f), a1 = f2u(0.f, 0.f);
            const ulonglong2* hv = (const ulonglong2*)sm->h[1];
            #pragma unroll
            for (int k = 0; k < 32; k++) {
                ulonglong2 v = hv[k];
                fma2(a0, v.x, w[2*k]);
                fma2(a1, v.y, w[2*k+1]);
            }
            sm->gh[1][j] = hsum(a0, a1);
            __syncthreads();
        }
    }

    // Epilogue: gates b1@(TT-1)
    if (isGate) {
        const float r = fsig(sm->gh[1][e]       + g1r);
        const float z = fsig(sm->gh[1][e + 128] + g1z);
        const float n = ftanh(g1n + r * sm->gh[1][e + 256]);
        hp1 = n + z * (hp1 - n);
        if (layer == 0)
            g_h0[((size_t)(TT - 1) * BB + b1) * HH + e] = hp1;
        hout[(size_t)b0 * HH + e] = hp0;
        hout[(size_t)b1 * HH + e] = hp1;
    }
    __syncthreads();
    if (layer == 0 && j == 0) red_rel(&g_f_h0[TT - 1]);
}

// ---------------------------------------------------------------------------
__global__ __launch_bounds__(384, 1) void gru_fused(
    const float* __restrict__ x,
    const float* __restrict__ W_ih0, const float* __restrict__ W_hh0,
    const float* __restrict__ b_ih0, const float* __restrict__ b_hh0,
    const float* __restrict__ W_ih1, const float* __restrict__ W_hh1,
    const float* __restrict__ b_ih1, const float* __restrict__ b_hh1,
    float* __restrict__ out)
{
    __shared__ __align__(16) SmemAll sm;
    const int bid = blockIdx.x;

    if (bid < N_REC) {
        rec_role(&sm, W_hh0, b_hh0, /*layer=*/0, bid, out);
    } else if (bid < 2 * N_REC) {
        rec_role(&sm, W_hh1, b_hh1, /*layer=*/1, bid - N_REC, out + BB * HH);
    } else if (bid < 2 * N_REC + N_G) {
        gemm_role(&sm, x, W_ih0, b_ih0, /*which=*/0, bid - 2 * N_REC);
    } else {
        gemm_role(&sm, nullptr, W_ih1, b_ih1, /*which=*/1, bid - 2 * N_REC - N_G);
    }
}

extern "C" void kernel_launch(void* const* d_in, const int* in_sizes, int n_in,
                              void* d_out, int out_size)
{
    const float* x     = (const float*)d_in[0];
    const float* W_ih0 = (const float*)d_in[1];
    const float* W_hh0 = (const float*)d_in[2];
    const float* b_ih0 = (const float*)d_in[3];
    const float* b_hh0 = (const float*)d_in[4];
    const float* W_ih1 = (const float*)d_in[5];
    const float* W_hh1 = (const float*)d_in[6];
    const float* b_ih1 = (const float*)d_in[7];
    const float* b_hh1 = (const float*)d_in[8];
    float* out = (float*)d_out;   // [L=2, B, H]

    zero_flags<<<(TT + 255) / 256, 256>>>();
    gru_fused<<<2 * N_REC + 2 * N_G, 384>>>(
        x, W_ih0, W_hh0, b_ih0, b_hh0, W_ih1, W_hh1, b_ih1, b_hh1, out);
}

// round 6
// speedup vs baseline: 1.0344x; 1.0344x over previous
#include <cuda_runtime.h>

#define BB 64
#define TT 4096
#define DD 128
#define HH 128
#define GG 384            // 3*H, gates [r, z, n]

#define N_REC 32          // rec CTAs per layer, 2 batches each
#define N_G   42          // gemm CTAs per layer
// roles: [0,32) rec0, [32,64) rec1, [64,106) gemm0, [106,148) gemm1

// Scratch (device globals — no allocation allowed).
__device__ float g_gi0[(size_t)TT * BB * GG];
__device__ float g_gi1[(size_t)TT * BB * GG];
__device__ float g_h0 [(size_t)TT * BB * HH];
__device__ unsigned g_f_gi0[TT];   // gi0[t] ready (target 1)
__device__ unsigned g_f_h0 [TT];   // h0[t] ready  (target N_REC)
__device__ unsigned g_f_gi1[TT];   // gi1[t] ready (target 1)

__device__ __forceinline__ float fsig(float x) {
    return __fdividef(1.0f, 1.0f + __expf(-x));
}
__device__ __forceinline__ float ftanh(float x) {
    return 1.0f - __fdividef(2.0f, __expf(2.0f * x) + 1.0f);
}

// ---- flag primitives (gpu-scope release/acquire) -------------------------
__device__ __forceinline__ unsigned ld_acq(const unsigned* p) {
    unsigned v;
    asm volatile("ld.acquire.gpu.global.b32 %0, [%1];" : "=r"(v) : "l"(p));
    return v;
}
__device__ __forceinline__ void red_rel(unsigned* p) {
    asm volatile("red.release.gpu.global.add.u32 [%0], 1;" :: "l"(p) : "memory");
}
__device__ __forceinline__ void spin_ge(const unsigned* p, unsigned target) {
    while (ld_acq(p) < target) { __nanosleep(64); }
}

__global__ void zero_flags() {
    int i = blockIdx.x * blockDim.x + threadIdx.x;
    if (i < TT) { g_f_gi0[i] = 0; g_f_h0[i] = 0; g_f_gi1[i] = 0; }
}

// ---------------------------------------------------------------------------
struct SmemRec {
    float h[2][128];      // per-batch hidden state
    float gh[2][384];     // per-batch pre-activation gh (+gi for r,z rows)
};
struct SmemGemm {
    float x[4][128];
};
union SmemAll { SmemRec r; SmemGemm g; };

// ---------------------------------------------------------------------------
// GEMM role: stream gi[t] = act_row @ W^T + bias for t = t0, t0+N_G, ...
//   which=0: act rows = x[b][t][:]  (no dependency)
//   which=1: act rows = h0[t][b][:] (wait g_f_h0[t] == N_REC)
// Scalar FFMA, weights in registers, rows broadcast from shared.
// ---------------------------------------------------------------------------
__device__ void gemm_role(SmemAll* sm,
                          const float* __restrict__ X,
                          const float* __restrict__ W,
                          const float* __restrict__ bias,
                          int which, int t0)
{
    const int j = threadIdx.x;

    float w[128];
    {
        const float4* wr = (const float4*)(W + (size_t)j * 128);
        #pragma unroll
        for (int k = 0; k < 32; k++) {
            float4 v = wr[k];
            w[4*k+0] = v.x; w[4*k+1] = v.y; w[4*k+2] = v.z; w[4*k+3] = v.w;
        }
    }
    const float bj = bias[j];
    float* dst = which ? g_gi1 : g_gi0;
    unsigned* fout = which ? g_f_gi1 : g_f_gi0;

    for (int t = t0; t < TT; t += N_G) {
        if (which == 1) {
            if (j == 0) spin_ge(&g_f_h0[t], N_REC);
        }
        __syncthreads();

        for (int m = 0; m < BB; m += 4) {
            for (int i = j; i < 4 * 128; i += 384) {
                const int r = i >> 7, c = i & 127;
                const int b = m + r;
                const float* src = which
                    ? (g_h0 + ((size_t)t * BB + b) * HH)
                    : (X + ((size_t)b * TT + t) * DD);
                sm->g.x[r][c] = src[c];
            }
            __syncthreads();

            float a0 = bj, a1 = bj, a2 = bj, a3 = bj;
            float e0 = 0.f, e1 = 0.f, e2 = 0.f, e3 = 0.f;
            const float4* r0 = (const float4*)sm->g.x[0];
            const float4* r1 = (const float4*)sm->g.x[1];
            const float4* r2 = (const float4*)sm->g.x[2];
            const float4* r3 = (const float4*)sm->g.x[3];
            #pragma unroll
            for (int k = 0; k < 32; k++) {
                float4 v0 = r0[k], v1 = r1[k], v2 = r2[k], v3 = r3[k];
                a0 = fmaf(v0.x, w[4*k+0], a0); e0 = fmaf(v0.y, w[4*k+1], e0);
                a0 = fmaf(v0.z, w[4*k+2], a0); e0 = fmaf(v0.w, w[4*k+3], e0);
                a1 = fmaf(v1.x, w[4*k+0], a1); e1 = fmaf(v1.y, w[4*k+1], e1);
                a1 = fmaf(v1.z, w[4*k+2], a1); e1 = fmaf(v1.w, w[4*k+3], e1);
                a2 = fmaf(v2.x, w[4*k+0], a2); e2 = fmaf(v2.y, w[4*k+1], e2);
                a2 = fmaf(v2.z, w[4*k+2], a2); e2 = fmaf(v2.w, w[4*k+3], e2);
                a3 = fmaf(v3.x, w[4*k+0], a3); e3 = fmaf(v3.y, w[4*k+1], e3);
                a3 = fmaf(v3.z, w[4*k+2], a3); e3 = fmaf(v3.w, w[4*k+3], e3);
            }
            dst[((size_t)t * BB + m + 0) * GG + j] = a0 + e0;
            dst[((size_t)t * BB + m + 1) * GG + j] = a1 + e1;
            dst[((size_t)t * BB + m + 2) * GG + j] = a2 + e2;
            dst[((size_t)t * BB + m + 3) * GG + j] = a3 + e3;
            __syncthreads();
        }
        if (j == 0) red_rel(&fout[t]);
    }
}

// ---------------------------------------------------------------------------
// REC role: sequential GRU for 2 batches (b0=2c, b1=2c+1), shared W_hh regs.
// Scalar FFMA dual-batch dot; gate math on threads 0-255 (R4 structure).
// ---------------------------------------------------------------------------
__device__ void rec_role(SmemAll* smu,
                         const float* __restrict__ Whh,
                         const float* __restrict__ bhh,
                         int layer, int c,
                         float* __restrict__ hout)
{
    SmemRec* sm = &smu->r;
    const int j = threadIdx.x;
    const int b0 = 2 * c, b1 = 2 * c + 1;

    float w[128];
    {
        const float4* wr = (const float4*)(Whh + (size_t)j * 128);
        #pragma unroll
        for (int k = 0; k < 32; k++) {
            float4 v = wr[k];
            w[4*k+0] = v.x; w[4*k+1] = v.y; w[4*k+2] = v.z; w[4*k+3] = v.w;
        }
    }
    const float bj = bhh[j];

    const float* gi = layer ? g_gi1 : g_gi0;
    const unsigned* fin = layer ? g_f_gi1 : g_f_gi0;

    const size_t S = (size_t)BB * GG;
    const bool isRZ = (j < 256);
    const int e  = j & 127;
    const int bl = (j >> 7) & 1;           // gate threads: local batch
    const int bglob = 2 * c + bl;

    const float* gp0 = gi + (size_t)b0 * GG + j;          // r,z-row gi streams
    const float* gp1 = gi + (size_t)b1 * GG + j;
    const float* pn  = gi + (size_t)bglob * GG + 256 + e; // gate thread: gi_n stream
    float* h0p = g_h0 + (size_t)bglob * HH + e;

    if (j < 128) { sm->h[0][j] = 0.0f; sm->h[1][j] = 0.0f; }
    if (j == 0) spin_ge(&fin[0], 1);
    __syncthreads();

    float gA = isRZ ? gp0[0] : 0.0f;
    float gB = isRZ ? gp1[0] : 0.0f;
    float gN = (j < 256) ? pn[0] : 0.0f;
    float hreg = 0.0f;

    for (int t = 0; t < TT; t++) {
        // --- dual-batch dot (scalar FFMA, 2 chains per batch) ---
        float a0 = bj, a1 = 0.f;           // batch b0
        float c0 = bj, c1 = 0.f;           // batch b1
        const float4* h0v = (const float4*)sm->h[0];
        const float4* h1v = (const float4*)sm->h[1];
        #pragma unroll
        for (int k = 0; k < 32; k++) {
            float4 v0 = h0v[k], v1 = h1v[k];
            a0 = fmaf(v0.x, w[4*k+0], a0); a1 = fmaf(v0.y, w[4*k+1], a1);
            a0 = fmaf(v0.z, w[4*k+2], a0); a1 = fmaf(v0.w, w[4*k+3], a1);
            c0 = fmaf(v1.x, w[4*k+0], c0); c1 = fmaf(v1.y, w[4*k+1], c1);
            c0 = fmaf(v1.z, w[4*k+2], c0); c1 = fmaf(v1.w, w[4*k+3], c1);
        }
        sm->gh[0][j] = (a0 + a1) + (isRZ ? gA : 0.0f);
        sm->gh[1][j] = (c0 + c1) + (isRZ ? gB : 0.0f);
        __syncthreads();                       // (A) gh ready

        // spare thread pre-verifies next step's gi flag during gate phase
        if (j == 383 && t + 1 < TT) spin_ge(&fin[t + 1], 1);

        if (j < 256) {
            const float gr  = sm->gh[bl][e];
            const float gz  = sm->gh[bl][e + 128];
            const float ghn = sm->gh[bl][e + 256];
            const float r = fsig(gr);
            const float z = fsig(gz);
            const float n = ftanh(gN + r * ghn);
            hreg = n + z * (hreg - n);
            sm->h[bl][e] = hreg;
            if (layer == 0) h0p[(size_t)t * BB * HH] = hreg;
        }
        __syncthreads();                       // (B) h published, flag known ready
        if (layer == 0 && j == 0) red_rel(&g_f_h0[t]);

        if (t + 1 < TT) {
            const size_t off = (size_t)(t + 1) * S;
            if (isRZ) { gA = gp0[off]; gB = gp1[off]; }
            if (j < 256) gN = pn[off];
        }
    }

    if (j < 256) hout[(size_t)bglob * HH + e] = hreg;
}

// ---------------------------------------------------------------------------
__global__ __launch_bounds__(384, 1) void gru_fused(
    const float* __restrict__ x,
    const float* __restrict__ W_ih0, const float* __restrict__ W_hh0,
    const float* __restrict__ b_ih0, const float* __restrict__ b_hh0,
    const float* __restrict__ W_ih1, const float* __restrict__ W_hh1,
    const float* __restrict__ b_ih1, const float* __restrict__ b_hh1,
    float* __restrict__ out)
{
    __shared__ __align__(16) SmemAll sm;
    const int bid = blockIdx.x;

    if (bid < N_REC) {
        rec_role(&sm, W_hh0, b_hh0, /*layer=*/0, bid, out);
    } else if (bid < 2 * N_REC) {
        rec_role(&sm, W_hh1, b_hh1, /*layer=*/1, bid - N_REC, out + BB * HH);
    } else if (bid < 2 * N_REC + N_G) {
        gemm_role(&sm, x, W_ih0, b_ih0, /*which=*/0, bid - 2 * N_REC);
    } else {
        gemm_role(&sm, nullptr, W_ih1, b_ih1, /*which=*/1, bid - 2 * N_REC - N_G);
    }
}

extern "C" void kernel_launch(void* const* d_in, const int* in_sizes, int n_in,
                              void* d_out, int out_size)
{
    const float* x     = (const float*)d_in[0];
    const float* W_ih0 = (const float*)d_in[1];
    const float* W_hh0 = (const float*)d_in[2];
    const float* b_ih0 = (const float*)d_in[3];
    const float* b_hh0 = (const float*)d_in[4];
    const float* W_ih1 = (const float*)d_in[5];
    const float* W_hh1 = (const float*)d_in[6];
    const float* b_ih1 = (const float*)d_in[7];
    const float* b_hh1 = (const float*)d_in[8];
    float* out = (float*)d_out;   // [L=2, B, H]

    zero_flags<<<(TT + 255) / 256, 256>>>();
    gru_fused<<<2 * N_REC + 2 * N_G, 384>>>(
        x, W_ih0, W_hh0, b_ih0, b_hh0, W_ih1, W_hh1, b_ih1, b_hh1, out);
}